// round 2
// baseline (speedup 1.0000x reference)
#include <cuda_runtime.h>
#include <math.h>

#define BB 4
#define TT 512
#define FF 257
#define MM 4
#define DD 128
#define PP 10
#define C2P 20
#define NLN (DD*FF)          // 32896
#define FCHUNK 130
#define FPITCH 132

// ---------------- device scratch (no allocations allowed) ----------------
__device__ float g_xs[(size_t)BB*TT*C2P*FF];   // features [B][T][C][F]  (~42 MB)
__device__ float g_mean[BB*FF*8];              // per (b,f): mean_r[4], mean_i[4]
__device__ float g_inv[BB*FF];                 // per (b,f): 1/norm

// ---------------- K1: time stats per (b, m, f) ----------------
// grid (B, ceil(F/32)), 256 threads = 32 f x 8 ch
__global__ void stats_kernel(const float* __restrict__ x) {
    int b  = blockIdx.x;
    int f0 = blockIdx.y * 32;
    int tid = threadIdx.x;
    int fi = tid >> 3;          // 0..31
    int ch = tid & 7;           // 0..7
    int f = f0 + fi;

    float s = 0.f, q = 0.f;
    if (f < FF) {
        const float* px = x + ((size_t)b * TT * FF + f) * 8 + ch;
        #pragma unroll 8
        for (int t = 0; t < TT; t++) {
            float v = px[(size_t)t * FF * 8];
            s += v; q += v * v;
        }
    }
    __shared__ float ss[32][8];
    __shared__ float sq[32][8];
    ss[fi][ch] = s; sq[fi][ch] = q;
    __syncthreads();

    if (tid < 32 && (f0 + tid) < FF) {
        int ff = f0 + tid;
        const float invT = 1.0f / (float)TT;
        float tot = 0.f, means[8];
        #pragma unroll
        for (int m = 0; m < 4; m++) {
            float mr = ss[tid][m]     * invT;
            float mi = ss[tid][m + 4] * invT;
            float pw = (sq[tid][m] + sq[tid][m + 4]) * invT - mr * mr - mi * mi;
            tot += pw;
            means[m] = mr; means[m + 4] = mi;
        }
        float inv = rsqrtf(fmaxf(tot, 1e-10f));
        #pragma unroll
        for (int j = 0; j < 8; j++) g_mean[(b * FF + ff) * 8 + j] = means[j];
        g_inv[b * FF + ff] = inv;
    }
}

// ---------------- K2: SCM pair features ----------------
// grid (B*T), 256 threads, each thread loops f
__global__ void feat_kernel(const float* __restrict__ x,
                            const float* __restrict__ expo,
                            const float* __restrict__ ipd) {
    int bt = blockIdx.x;
    int b  = bt / TT;

    for (int f = threadIdx.x; f < FF; f += blockDim.x) {
        const float* px = x + ((size_t)bt * FF + f) * 8;
        const float* mn = g_mean + (b * FF + f) * 8;
        float inv = g_inv[b * FF + f];

        float vr[4], vi[4];
        #pragma unroll
        for (int m = 0; m < 4; m++) {
            vr[m] = (px[m]     - mn[m])     * inv;
            vi[m] = (px[m + 4] - mn[m + 4]) * inv;
        }
        float s1 = 1.0f / (1.0f + expf(-expo[f]));
        float s2 = 1.0f / (1.0f + expf(-ipd[f]));

        const int ia[10] = {0,0,0,0,1,1,1,2,2,3};
        const int ja[10] = {0,1,2,3,1,2,3,2,3,3};
        float* ob = g_xs + (size_t)bt * C2P * FF + f;

        #pragma unroll
        for (int p = 0; p < 10; p++) {
            float re = vr[ia[p]] * vr[ja[p]] + vi[ia[p]] * vi[ja[p]];
            float im = vi[ia[p]] * vr[ja[p]] - vr[ia[p]] * vi[ja[p]];
            float a  = sqrtf(re * re + im * im);
            float beta = powf(a, s1);
            float mag  = a / (beta + 1e-10f);
            float ang  = atan2f(im, re) * s2;
            float sn, cs;
            sincosf(ang, &sn, &cs);
            ob[(size_t)(2 * p)     * FF] = mag * cs;
            ob[(size_t)(2 * p + 1) * FF] = mag * sn;
        }
    }
}

// ---------------- K3: fused conv1d (SAME, K=5) + LayerNorm ----------------
// grid (B*T), 256 threads = 128 d x 2 f-halves.
// Dynamic smem: y[128][257] + in[100][FPITCH] + red[64]
// Input staging rows are ordered (c outer, k inner) to match conv_w's
// [D][2P][5] flattening: w[j] = conv_w[d][c][k] with j = c*5 + k.
extern __shared__ float smem[];

__global__ void __launch_bounds__(256, 1)
conv_ln_kernel(const float* __restrict__ conv_w,
               const float* __restrict__ conv_b,
               const float* __restrict__ ln_w,
               const float* __restrict__ ln_b,
               float* __restrict__ out) {
    int bt = blockIdx.x;
    int b  = bt / TT;
    int t  = bt % TT;
    int tid = threadIdx.x;

    float* y_s  = smem;                 // 32896
    float* in_s = smem + NLN;           // 100*FPITCH = 13200
    float* red  = in_s + 100 * FPITCH;  // 64

    // Stage weights coalesced into smem (reuses in_s region), then to regs.
    for (int i = tid; i < DD * C2P * 5; i += 256) in_s[i] = conv_w[i];
    __syncthreads();

    int d = tid & 127;
    int h = tid >> 7;
    float w[100];
    #pragma unroll
    for (int j = 0; j < 100; j++) w[j] = in_s[d * 100 + j];
    float bias = conv_b[d];
    __syncthreads();

    for (int pass = 0; pass < 2; pass++) {
        int f0 = pass * FCHUNK;
        int fc = (FF - f0 < FCHUNK) ? (FF - f0) : FCHUNK;

        // cooperative load of 100 rows (kc = c*5 + k) x fc, zero-padded in t
        int total = 100 * fc;
        for (int li = tid; li < total; li += 256) {
            int kc = li / fc;
            int fl = li - kc * fc;
            int c  = kc / 5;          // channel (matches weight outer dim)
            int k  = kc - c * 5;      // tap (matches weight inner dim)
            int tt = t + k - 2;
            float v = 0.f;
            if (tt >= 0 && tt < TT)
                v = g_xs[((size_t)(b * TT + tt) * C2P + c) * FF + f0 + fl];
            in_s[kc * FPITCH + fl] = v;
        }
        __syncthreads();

        for (int fl = h; fl < fc; fl += 2) {
            float a0 = bias, a1 = 0.f, a2 = 0.f, a3 = 0.f;
            const float* sp = in_s + fl;
            #pragma unroll
            for (int j = 0; j < 100; j += 4) {
                a0 = fmaf(w[j    ], sp[(j    ) * FPITCH], a0);
                a1 = fmaf(w[j + 1], sp[(j + 1) * FPITCH], a1);
                a2 = fmaf(w[j + 2], sp[(j + 2) * FPITCH], a2);
                a3 = fmaf(w[j + 3], sp[(j + 3) * FPITCH], a3);
            }
            y_s[d * FF + f0 + fl] = (a0 + a1) + (a2 + a3);
        }
        __syncthreads();
    }

    // LayerNorm stats over all 32896 values
    float s = 0.f, q = 0.f;
    for (int i = tid; i < NLN; i += 256) {
        float v = y_s[i];
        s += v; q += v * v;
    }
    #pragma unroll
    for (int o = 16; o > 0; o >>= 1) {
        s += __shfl_xor_sync(0xffffffffu, s, o);
        q += __shfl_xor_sync(0xffffffffu, q, o);
    }
    if ((tid & 31) == 0) { red[tid >> 5] = s; red[8 + (tid >> 5)] = q; }
    __syncthreads();
    if (tid < 32) {
        s = (tid < 8) ? red[tid] : 0.f;
        q = (tid < 8) ? red[8 + tid] : 0.f;
        #pragma unroll
        for (int o = 4; o > 0; o >>= 1) {
            s += __shfl_xor_sync(0xffffffffu, s, o);
            q += __shfl_xor_sync(0xffffffffu, q, o);
        }
        if (tid == 0) {
            const float invN = 1.0f / (float)NLN;
            float mu  = s * invN;
            float var = q * invN - mu * mu;
            red[16] = mu;
            red[17] = rsqrtf(var + 1e-5f);
        }
    }
    __syncthreads();
    float mu = red[16], rs = red[17];

    float* po = out + (size_t)bt * NLN;
    for (int i = tid; i < NLN; i += 256) {
        po[i] = (y_s[i] - mu) * rs * ln_w[i] + ln_b[i];
    }
}

// ---------------- launch ----------------
extern "C" void kernel_launch(void* const* d_in, const int* in_sizes, int n_in,
                              void* d_out, int out_size) {
    const float* x    = (const float*)d_in[0];
    const float* expo = (const float*)d_in[1];
    const float* ipd  = (const float*)d_in[2];
    const float* cw   = (const float*)d_in[3];
    const float* cb   = (const float*)d_in[4];
    const float* lw   = (const float*)d_in[5];
    const float* lb   = (const float*)d_in[6];
    float* out = (float*)d_out;

    stats_kernel<<<dim3(BB, (FF + 31) / 32), 256>>>(x);
    feat_kernel<<<BB * TT, 256>>>(x, expo, ipd);

    int smem_bytes = (NLN + 100 * FPITCH + 64) * (int)sizeof(float); // 184,640 B
    cudaFuncSetAttribute(conv_ln_kernel,
                         cudaFuncAttributeMaxDynamicSharedMemorySize, smem_bytes);
    conv_ln_kernel<<<BB * TT, 256, smem_bytes>>>(cw, cb, lw, lb, out);
}

// round 3
// speedup vs baseline: 1.3278x; 1.3278x over previous
#include <cuda_runtime.h>
#include <math.h>

#define BB 4
#define TT 512
#define FF 257
#define DD 128
#define C2P 20
#define NLN (DD*FF)          // 32896
#define YP 260               // padded y row (multiple of 4)
#define WIN 136              // padded in_s row (floats), 544B per row
#define NTH 384

// ---------------- device scratch ----------------
__device__ float g_xs[(size_t)BB*TT*C2P*FF];   // features [B][T][C][F]  (~42 MB)
__device__ float g_mean[BB*FF*8];
__device__ float g_inv[BB*FF];

// ---------------- K1: time stats, one block per (b,f) ----------------
__global__ void stats_kernel(const float* __restrict__ x) {
    int b = blockIdx.x;
    int f = blockIdx.y;
    int tid = threadIdx.x;          // 256
    int ch = tid & 7;
    int tl = tid >> 3;              // 0..31

    float s = 0.f, q = 0.f;
    const float* px = x + ((size_t)b * TT * FF + f) * 8 + ch;
    #pragma unroll 4
    for (int t = tl; t < TT; t += 32) {
        float v = px[(size_t)t * FF * 8];
        s += v; q += v * v;
    }
    // reduce over tl bits inside warp (lane = (tl&3)*8 + ch)
    s += __shfl_xor_sync(0xffffffffu, s, 8);
    q += __shfl_xor_sync(0xffffffffu, q, 8);
    s += __shfl_xor_sync(0xffffffffu, s, 16);
    q += __shfl_xor_sync(0xffffffffu, q, 16);

    __shared__ float sb[8][8], qb[8][8];
    int warp = tid >> 5, lane = tid & 31;
    if (lane < 8) { sb[warp][lane] = s; qb[warp][lane] = q; }
    __syncthreads();

    if (tid == 0) {
        const float invT = 1.0f / (float)TT;
        float ssum[8], qsum[8];
        #pragma unroll
        for (int c = 0; c < 8; c++) {
            float a = 0.f, bq = 0.f;
            #pragma unroll
            for (int w = 0; w < 8; w++) { a += sb[w][c]; bq += qb[w][c]; }
            ssum[c] = a * invT; qsum[c] = bq * invT;
        }
        float tot = 0.f;
        #pragma unroll
        for (int m = 0; m < 4; m++) {
            float mr = ssum[m], mi = ssum[m + 4];
            tot += qsum[m] + qsum[m + 4] - mr * mr - mi * mi;
        }
        #pragma unroll
        for (int j = 0; j < 8; j++) g_mean[(b * FF + f) * 8 + j] = ssum[j];
        g_inv[b * FF + f] = rsqrtf(fmaxf(tot, 1e-10f));
    }
}

// ---------------- K2: SCM pair features ----------------
__global__ void feat_kernel(const float* __restrict__ x,
                            const float* __restrict__ expo,
                            const float* __restrict__ ipd) {
    int bt = blockIdx.x;
    int b  = bt / TT;

    for (int f = threadIdx.x; f < FF; f += blockDim.x) {
        const float* px = x + ((size_t)bt * FF + f) * 8;
        const float* mn = g_mean + (b * FF + f) * 8;
        float inv = g_inv[b * FF + f];

        float vr[4], vi[4];
        #pragma unroll
        for (int m = 0; m < 4; m++) {
            vr[m] = (px[m]     - mn[m])     * inv;
            vi[m] = (px[m + 4] - mn[m + 4]) * inv;
        }
        float s1 = 1.0f / (1.0f + expf(-expo[f]));
        float s2 = 1.0f / (1.0f + expf(-ipd[f]));

        const int ia[10] = {0,0,0,0,1,1,1,2,2,3};
        const int ja[10] = {0,1,2,3,1,2,3,2,3,3};
        float* ob = g_xs + (size_t)bt * C2P * FF + f;

        #pragma unroll
        for (int p = 0; p < 10; p++) {
            float re = vr[ia[p]] * vr[ja[p]] + vi[ia[p]] * vi[ja[p]];
            float im = vi[ia[p]] * vr[ja[p]] - vr[ia[p]] * vi[ja[p]];
            float a  = sqrtf(re * re + im * im);
            float beta = (a > 0.f) ? exp2f(s1 * log2f(a)) : 0.f;
            float mag  = a / (beta + 1e-10f);
            float ang  = atan2f(im, re) * s2;
            float sn, cs;
            sincosf(ang, &sn, &cs);
            ob[(size_t)(2 * p)     * FF] = mag * cs;
            ob[(size_t)(2 * p + 1) * FF] = mag * sn;
        }
    }
}

// ---------------- K3: fused conv1d (SAME,K=5) + LayerNorm ----------------
// 384 threads = 128 d x 3 f-quad groups. LDS.128 per tap (4 f at once).
extern __shared__ float smem[];

__global__ void __launch_bounds__(NTH, 1)
conv_ln_kernel(const float* __restrict__ conv_w,
               const float* __restrict__ conv_b,
               const float* __restrict__ ln_w,
               const float* __restrict__ ln_b,
               float* __restrict__ out) {
    int bt = blockIdx.x;
    int b  = bt / TT;
    int t  = bt % TT;
    int tid = threadIdx.x;

    float* y_s  = smem;                  // DD*YP = 33280
    float* in_s = smem + DD * YP;        // 100*WIN = 13600
    float* red  = in_s + 100 * WIN;      // 32

    // stage weights coalesced, then to regs (w[j] = conv_w[d][c][k], j=c*5+k)
    for (int i = tid; i < DD * 100; i += NTH) in_s[i] = conv_w[i];
    __syncthreads();

    int d = tid & 127;
    int q = tid >> 7;                    // 0..2
    float w[100];
    #pragma unroll
    for (int j = 0; j < 100; j++) w[j] = in_s[d * 100 + j];
    float bias = conv_b[d];
    __syncthreads();

    const int f0s[2] = {0, 132};
    const int fcs[2] = {132, 125};

    #pragma unroll
    for (int pass = 0; pass < 2; pass++) {
        int f0 = f0s[pass];
        int fc = fcs[pass];
        int nq = (fc + 3) >> 2;          // 33, 32
        int wcols = nq * 4;              // 132, 128

        // stage input rows kc = c*5+k (matching weight flattening), zero-padded
        int total = 100 * wcols;
        for (int li = tid; li < total; li += NTH) {
            int kc = li / wcols;
            int fl = li - kc * wcols;
            int c  = kc / 5;
            int k  = kc - c * 5;
            int tt = t + k - 2;
            float v = 0.f;
            if (tt >= 0 && tt < TT && fl < fc)
                v = g_xs[((size_t)(b * TT + tt) * C2P + c) * FF + f0 + fl];
            in_s[kc * WIN + fl] = v;
        }
        __syncthreads();

        for (int qi = q; qi < nq; qi += 3) {
            const float4* sp = (const float4*)(in_s + qi * 4);
            float4 c0 = {0,0,0,0}, c1 = {0,0,0,0}, c2 = {0,0,0,0}, c3 = {0,0,0,0};
            #pragma unroll
            for (int j = 0; j < 100; j += 4) {
                float4 v0 = sp[(j + 0) * (WIN / 4)];
                float4 v1 = sp[(j + 1) * (WIN / 4)];
                float4 v2 = sp[(j + 2) * (WIN / 4)];
                float4 v3 = sp[(j + 3) * (WIN / 4)];
                c0.x = fmaf(w[j], v0.x, c0.x); c0.y = fmaf(w[j], v0.y, c0.y);
                c0.z = fmaf(w[j], v0.z, c0.z); c0.w = fmaf(w[j], v0.w, c0.w);
                c1.x = fmaf(w[j+1], v1.x, c1.x); c1.y = fmaf(w[j+1], v1.y, c1.y);
                c1.z = fmaf(w[j+1], v1.z, c1.z); c1.w = fmaf(w[j+1], v1.w, c1.w);
                c2.x = fmaf(w[j+2], v2.x, c2.x); c2.y = fmaf(w[j+2], v2.y, c2.y);
                c2.z = fmaf(w[j+2], v2.z, c2.z); c2.w = fmaf(w[j+2], v2.w, c2.w);
                c3.x = fmaf(w[j+3], v3.x, c3.x); c3.y = fmaf(w[j+3], v3.y, c3.y);
                c3.z = fmaf(w[j+3], v3.z, c3.z); c3.w = fmaf(w[j+3], v3.w, c3.w);
            }
            float4 r;
            r.x = bias + (c0.x + c1.x) + (c2.x + c3.x);
            r.y = bias + (c0.y + c1.y) + (c2.y + c3.y);
            r.z = bias + (c0.z + c1.z) + (c2.z + c3.z);
            r.w = bias + (c0.w + c1.w) + (c2.w + c3.w);
            *(float4*)(y_s + d * YP + f0 + qi * 4) = r;   // 16B aligned (YP%4==0)
        }
        __syncthreads();
    }

    // LayerNorm stats over valid 128x257 region
    int warp = tid >> 5, lane = tid & 31;
    float s = 0.f, qs = 0.f;
    for (int r = warp; r < DD; r += 12)
        for (int cc = lane; cc < FF; cc += 32) {
            float v = y_s[r * YP + cc];
            s += v; qs += v * v;
        }
    #pragma unroll
    for (int o = 16; o > 0; o >>= 1) {
        s  += __shfl_xor_sync(0xffffffffu, s, o);
        qs += __shfl_xor_sync(0xffffffffu, qs, o);
    }
    if (lane == 0) { red[warp] = s; red[16 + warp] = qs; }
    __syncthreads();
    if (tid < 32) {
        s  = (tid < 12) ? red[tid] : 0.f;
        qs = (tid < 12) ? red[16 + tid] : 0.f;
        #pragma unroll
        for (int o = 8; o > 0; o >>= 1) {
            s  += __shfl_xor_sync(0xffffffffu, s, o);
            qs += __shfl_xor_sync(0xffffffffu, qs, o);
        }
        if (tid == 0) {
            const float invN = 1.0f / (float)NLN;
            float mu  = s * invN;
            float var = qs * invN - mu * mu;
            red[30] = mu;
            red[31] = rsqrtf(var + 1e-5f);
        }
    }
    __syncthreads();
    float mu = red[30], rs = red[31];

    float* po = out + (size_t)bt * NLN;
    for (int r = warp; r < DD; r += 12)
        for (int cc = lane; cc < FF; cc += 32) {
            int oi = r * FF + cc;
            po[oi] = (y_s[r * YP + cc] - mu) * rs * ln_w[oi] + ln_b[oi];
        }
}

// ---------------- launch ----------------
extern "C" void kernel_launch(void* const* d_in, const int* in_sizes, int n_in,
                              void* d_out, int out_size) {
    const float* x    = (const float*)d_in[0];
    const float* expo = (const float*)d_in[1];
    const float* ipd  = (const float*)d_in[2];
    const float* cw   = (const float*)d_in[3];
    const float* cb   = (const float*)d_in[4];
    const float* lw   = (const float*)d_in[5];
    const float* lb   = (const float*)d_in[6];
    float* out = (float*)d_out;

    stats_kernel<<<dim3(BB, FF), 256>>>(x);
    feat_kernel<<<BB * TT, 256>>>(x, expo, ipd);

    int smem_bytes = (DD * YP + 100 * WIN + 32) * (int)sizeof(float); // 187,648 B
    cudaFuncSetAttribute(conv_ln_kernel,
                         cudaFuncAttributeMaxDynamicSharedMemorySize, smem_bytes);
    conv_ln_kernel<<<BB * TT, NTH, smem_bytes>>>(cw, cb, lw, lb, out);
}

// round 4
// speedup vs baseline: 1.6925x; 1.2747x over previous
#include <cuda_runtime.h>
#include <math.h>

#define BB 4
#define TT 512
#define FF 257
#define DD 128
#define C2P 20
#define NLN (DD*FF)          // 32896
#define YP 260
#define WIN2 68              // in_s row width (floats), 272B, 16B-aligned
#define NTH 512

typedef unsigned long long ull;

__device__ __forceinline__ void fma2(ull &acc, ull a, ull b) {
    asm("fma.rn.f32x2 %0, %1, %2, %0;" : "+l"(acc) : "l"(a), "l"(b));
}
__device__ __forceinline__ ull pack2(float v) {
    ull r; unsigned u = __float_as_uint(v);
    asm("mov.b64 %0, {%1, %1};" : "=l"(r) : "r"(u));
    return r;
}
__device__ __forceinline__ float2 unpack2(ull v) {
    unsigned lo, hi;
    asm("mov.b64 {%0, %1}, %2;" : "=r"(lo), "=r"(hi) : "l"(v));
    return make_float2(__uint_as_float(lo), __uint_as_float(hi));
}

// ---------------- device scratch ----------------
__device__ float g_xs[(size_t)BB*TT*C2P*FF];   // features [B][T][C][F]
__device__ float g_mean[BB*FF*8];
__device__ float g_inv[BB*FF];
__device__ float g_wt[100*DD];                 // transposed weights [j][d]

// ---------------- K0: weight transpose (once, tiny) ----------------
__global__ void wtrans_kernel(const float* __restrict__ conv_w) {
    for (int i = threadIdx.x; i < DD * 100; i += blockDim.x) {
        int d = i / 100, j = i - d * 100;
        g_wt[j * DD + d] = conv_w[i];
    }
}

// ---------------- K1: time stats, one block per (b,f) ----------------
__global__ void stats_kernel(const float* __restrict__ x) {
    int b = blockIdx.x;
    int f = blockIdx.y;
    int tid = threadIdx.x;          // 256
    int ch = tid & 7;
    int tl = tid >> 3;

    float s = 0.f, q = 0.f;
    const float* px = x + ((size_t)b * TT * FF + f) * 8 + ch;
    #pragma unroll 4
    for (int t = tl; t < TT; t += 32) {
        float v = px[(size_t)t * FF * 8];
        s += v; q += v * v;
    }
    s += __shfl_xor_sync(0xffffffffu, s, 8);
    q += __shfl_xor_sync(0xffffffffu, q, 8);
    s += __shfl_xor_sync(0xffffffffu, s, 16);
    q += __shfl_xor_sync(0xffffffffu, q, 16);

    __shared__ float sb[8][8], qb[8][8];
    int warp = tid >> 5, lane = tid & 31;
    if (lane < 8) { sb[warp][lane] = s; qb[warp][lane] = q; }
    __syncthreads();

    if (tid == 0) {
        const float invT = 1.0f / (float)TT;
        float ssum[8], qsum[8];
        #pragma unroll
        for (int c = 0; c < 8; c++) {
            float a = 0.f, bq = 0.f;
            #pragma unroll
            for (int w = 0; w < 8; w++) { a += sb[w][c]; bq += qb[w][c]; }
            ssum[c] = a * invT; qsum[c] = bq * invT;
        }
        float tot = 0.f;
        #pragma unroll
        for (int m = 0; m < 4; m++) {
            float mr = ssum[m], mi = ssum[m + 4];
            tot += qsum[m] + qsum[m + 4] - mr * mr - mi * mi;
        }
        #pragma unroll
        for (int j = 0; j < 8; j++) g_mean[(b * FF + f) * 8 + j] = ssum[j];
        g_inv[b * FF + f] = rsqrtf(fmaxf(tot, 1e-10f));
    }
}

// ---------------- K2: SCM pair features ----------------
__global__ void feat_kernel(const float* __restrict__ x,
                            const float* __restrict__ expo,
                            const float* __restrict__ ipd) {
    int bt = blockIdx.x;
    int b  = bt / TT;

    for (int f = threadIdx.x; f < FF; f += blockDim.x) {
        const float* px = x + ((size_t)bt * FF + f) * 8;
        const float* mn = g_mean + (b * FF + f) * 8;
        float inv = g_inv[b * FF + f];

        float vr[4], vi[4];
        #pragma unroll
        for (int m = 0; m < 4; m++) {
            vr[m] = (px[m]     - mn[m])     * inv;
            vi[m] = (px[m + 4] - mn[m + 4]) * inv;
        }
        float s1 = 1.0f / (1.0f + expf(-expo[f]));
        float s2 = 1.0f / (1.0f + expf(-ipd[f]));

        const int ia[10] = {0,0,0,0,1,1,1,2,2,3};
        const int ja[10] = {0,1,2,3,1,2,3,2,3,3};
        float* ob = g_xs + (size_t)bt * C2P * FF + f;

        #pragma unroll
        for (int p = 0; p < 10; p++) {
            float re = vr[ia[p]] * vr[ja[p]] + vi[ia[p]] * vi[ja[p]];
            float im = vi[ia[p]] * vr[ja[p]] - vr[ia[p]] * vi[ja[p]];
            float a  = sqrtf(re * re + im * im);
            float beta = (a > 0.f) ? exp2f(s1 * log2f(a)) : 0.f;
            float mag  = a / (beta + 1e-10f);
            float ang  = atan2f(im, re) * s2;
            float sn, cs;
            sincosf(ang, &sn, &cs);
            ob[(size_t)(2 * p)     * FF] = mag * cs;
            ob[(size_t)(2 * p + 1) * FF] = mag * sn;
        }
    }
}

// ---------------- K3: fused conv1d (SAME,K=5) + LayerNorm ----------------
// 512 threads = 64 d-pairs x 8 f-quad groups; 4 f-passes of 68 cols.
// j outer (weights via LDS.64 from transposed smem), quads inner, FFMA2.
extern __shared__ float smem[];

__global__ void __launch_bounds__(NTH, 1)
conv_ln_kernel(const float* __restrict__ conv_b,
               const float* __restrict__ ln_w,
               const float* __restrict__ ln_b,
               float* __restrict__ out) {
    int bt = blockIdx.x;
    int b  = bt / TT;
    int t  = bt % TT;
    int tid = threadIdx.x;

    float* y_s  = smem;                     // DD*YP   = 33280 floats
    float* w_s  = smem + DD * YP;           // 100*128 = 12800
    float* in_s = w_s + 100 * DD;           // 100*68  =  6800
    float* red  = in_s + 100 * WIN2;        // 40

    // stage transposed weights (coalesced LDG, conflict-free STS)
    for (int i = tid; i < 100 * DD; i += NTH) w_s[i] = g_wt[i];

    int dp = tid & 63;            // d-pair index
    int q  = tid >> 6;            // 0..7 (uniform per warp)
    int d0 = 2 * dp, d1 = 2 * dp + 1;
    float2 bb = *(const float2*)(conv_b + d0);
    bool do3 = (q == 0);          // third quad (qi=16) only for q==0
    __syncthreads();

    #pragma unroll
    for (int pass = 0; pass < 4; pass++) {
        int f0 = pass * WIN2;

        // stage input rows j = c*5+k (matches conv_w [D][2P][5] flattening)
        for (int li = tid; li < 100 * WIN2; li += NTH) {
            int kc = li / WIN2;
            int fl = li - kc * WIN2;
            int c  = kc / 5;
            int k  = kc - c * 5;
            int tt = t + k - 2;
            int f  = f0 + fl;
            float v = 0.f;
            if (tt >= 0 && tt < TT && f < FF)
                v = g_xs[((size_t)(b * TT + tt) * C2P + c) * FF + f];
            in_s[kc * WIN2 + fl] = v;
        }
        __syncthreads();

        ull a00=0,a01=0,a02=0,a03=0;   // u=0: d0{lo,hi}, d1{lo,hi}
        ull a10=0,a11=0,a12=0,a13=0;   // u=1
        ull a20=0,a21=0,a22=0,a23=0;   // u=2 (q==0 only)

        #pragma unroll 5
        for (int j = 0; j < 100; j++) {
            float2 wv = *(const float2*)(w_s + j * DD + d0);
            ull w0 = pack2(wv.x);
            ull w1 = pack2(wv.y);
            const float* row = in_s + j * WIN2;

            ulonglong2 v0 = *(const ulonglong2*)(row + 4 * q);
            fma2(a00, w0, v0.x); fma2(a01, w0, v0.y);
            fma2(a02, w1, v0.x); fma2(a03, w1, v0.y);

            ulonglong2 v1 = *(const ulonglong2*)(row + 4 * (q + 8));
            fma2(a10, w0, v1.x); fma2(a11, w0, v1.y);
            fma2(a12, w1, v1.x); fma2(a13, w1, v1.y);

            if (do3) {
                ulonglong2 v2 = *(const ulonglong2*)(row + 4 * 16);
                fma2(a20, w0, v2.x); fma2(a21, w0, v2.y);
                fma2(a22, w1, v2.x); fma2(a23, w1, v2.y);
            }
        }

        // store quads to y_s (+bias); guard f<257 keeps rows within YP
        {
            int f = f0 + 4 * q;
            if (f < FF) {
                float2 p0 = unpack2(a00), p1 = unpack2(a01);
                float2 p2 = unpack2(a02), p3 = unpack2(a03);
                *(float4*)(y_s + d0 * YP + f) =
                    make_float4(p0.x + bb.x, p0.y + bb.x, p1.x + bb.x, p1.y + bb.x);
                *(float4*)(y_s + d1 * YP + f) =
                    make_float4(p2.x + bb.y, p2.y + bb.y, p3.x + bb.y, p3.y + bb.y);
            }
            f = f0 + 4 * (q + 8);
            if (f < FF) {
                float2 p0 = unpack2(a10), p1 = unpack2(a11);
                float2 p2 = unpack2(a12), p3 = unpack2(a13);
                *(float4*)(y_s + d0 * YP + f) =
                    make_float4(p0.x + bb.x, p0.y + bb.x, p1.x + bb.x, p1.y + bb.x);
                *(float4*)(y_s + d1 * YP + f) =
                    make_float4(p2.x + bb.y, p2.y + bb.y, p3.x + bb.y, p3.y + bb.y);
            }
            f = f0 + 64;
            if (do3 && f < FF) {
                float2 p0 = unpack2(a20), p1 = unpack2(a21);
                float2 p2 = unpack2(a22), p3 = unpack2(a23);
                *(float4*)(y_s + d0 * YP + f) =
                    make_float4(p0.x + bb.x, p0.y + bb.x, p1.x + bb.x, p1.y + bb.x);
                *(float4*)(y_s + d1 * YP + f) =
                    make_float4(p2.x + bb.y, p2.y + bb.y, p3.x + bb.y, p3.y + bb.y);
            }
        }
        __syncthreads();
    }

    // LayerNorm over valid 128x257 region of y_s
    int warp = tid >> 5, lane = tid & 31;
    float s = 0.f, qs = 0.f;
    for (int r = warp; r < DD; r += 16)
        for (int cc = lane; cc < FF; cc += 32) {
            float v = y_s[r * YP + cc];
            s += v; qs += v * v;
        }
    #pragma unroll
    for (int o = 16; o > 0; o >>= 1) {
        s  += __shfl_xor_sync(0xffffffffu, s, o);
        qs += __shfl_xor_sync(0xffffffffu, qs, o);
    }
    if (lane == 0) { red[warp] = s; red[16 + warp] = qs; }
    __syncthreads();
    if (tid < 32) {
        s  = (tid < 16) ? red[tid] : 0.f;
        qs = (tid < 16) ? red[16 + tid] : 0.f;
        #pragma unroll
        for (int o = 8; o > 0; o >>= 1) {
            s  += __shfl_xor_sync(0xffffffffu, s, o);
            qs += __shfl_xor_sync(0xffffffffu, qs, o);
        }
        if (tid == 0) {
            const float invN = 1.0f / (float)NLN;
            float mu  = s * invN;
            float var = qs * invN - mu * mu;
            red[32] = mu;
            red[33] = rsqrtf(var + 1e-5f);
        }
    }
    __syncthreads();
    float mu = red[32], rs = red[33];

    float* po = out + (size_t)bt * NLN;
    for (int r = warp; r < DD; r += 16)
        for (int cc = lane; cc < FF; cc += 32) {
            int oi = r * FF + cc;
            po[oi] = (y_s[r * YP + cc] - mu) * rs * ln_w[oi] + ln_b[oi];
        }
}

// ---------------- launch ----------------
extern "C" void kernel_launch(void* const* d_in, const int* in_sizes, int n_in,
                              void* d_out, int out_size) {
    const float* x    = (const float*)d_in[0];
    const float* expo = (const float*)d_in[1];
    const float* ipd  = (const float*)d_in[2];
    const float* cw   = (const float*)d_in[3];
    const float* cb   = (const float*)d_in[4];
    const float* lw   = (const float*)d_in[5];
    const float* lb   = (const float*)d_in[6];
    float* out = (float*)d_out;

    wtrans_kernel<<<1, 256>>>(cw);
    stats_kernel<<<dim3(BB, FF), 256>>>(x);
    feat_kernel<<<BB * TT, 256>>>(x, expo, ipd);

    int smem_bytes = (DD * YP + 100 * DD + 100 * WIN2 + 40) * (int)sizeof(float); // 211,680 B
    cudaFuncSetAttribute(conv_ln_kernel,
                         cudaFuncAttributeMaxDynamicSharedMemorySize, smem_bytes);
    conv_ln_kernel<<<BB * TT, NTH, smem_bytes>>>(cb, lw, lb, out);
}

// round 5
// speedup vs baseline: 2.2583x; 1.3343x over previous
#include <cuda_runtime.h>
#include <math.h>

#define BB 4
#define TT 512
#define FF 257
#define DD 128
#define C2P 20
#define NLN (DD*FF)          // 32896
#define NTH 512

typedef unsigned long long ull;

__device__ __forceinline__ void fma2(ull &acc, ull a, ull b) {
    asm("fma.rn.f32x2 %0, %1, %2, %0;" : "+l"(acc) : "l"(a), "l"(b));
}
__device__ __forceinline__ ull pack2(float v) {
    ull r; unsigned u = __float_as_uint(v);
    asm("mov.b64 %0, {%1, %1};" : "=l"(r) : "r"(u));
    return r;
}
__device__ __forceinline__ ull packab(float a, float b) {
    ull r;
    asm("mov.b64 %0, {%1, %2};" : "=l"(r) : "r"(__float_as_uint(a)), "r"(__float_as_uint(b)));
    return r;
}
__device__ __forceinline__ float2 unpack2(ull v) {
    unsigned lo, hi;
    asm("mov.b64 {%0, %1}, %2;" : "=r"(lo), "=r"(hi) : "l"(v));
    return make_float2(__uint_as_float(lo), __uint_as_float(hi));
}

// ---------------- device scratch ----------------
__device__ float g_xs[(size_t)BB*TT*C2P*FF];   // features [B][T][C][F]
__device__ float g_mean[BB*FF*8];
__device__ float g_inv[BB*FF];
__device__ float g_wt[100*DD];                 // transposed weights [j][d]

// ---------------- K0: weight transpose ----------------
__global__ void wtrans_kernel(const float* __restrict__ conv_w) {
    for (int i = threadIdx.x; i < DD * 100; i += blockDim.x) {
        int d = i / 100, j = i - d * 100;
        g_wt[j * DD + d] = conv_w[i];
    }
}

// ---------------- K1: time stats, one block per (b,f) ----------------
__global__ void stats_kernel(const float* __restrict__ x) {
    int b = blockIdx.x;
    int f = blockIdx.y;
    int tid = threadIdx.x;          // 256
    int ch = tid & 7;
    int tl = tid >> 3;

    float s = 0.f, q = 0.f;
    const float* px = x + ((size_t)b * TT * FF + f) * 8 + ch;
    #pragma unroll 4
    for (int t = tl; t < TT; t += 32) {
        float v = px[(size_t)t * FF * 8];
        s += v; q += v * v;
    }
    s += __shfl_xor_sync(0xffffffffu, s, 8);
    q += __shfl_xor_sync(0xffffffffu, q, 8);
    s += __shfl_xor_sync(0xffffffffu, s, 16);
    q += __shfl_xor_sync(0xffffffffu, q, 16);

    __shared__ float sb[8][8], qb[8][8];
    int warp = tid >> 5, lane = tid & 31;
    if (lane < 8) { sb[warp][lane] = s; qb[warp][lane] = q; }
    __syncthreads();

    if (tid == 0) {
        const float invT = 1.0f / (float)TT;
        float ssum[8], qsum[8];
        #pragma unroll
        for (int c = 0; c < 8; c++) {
            float a = 0.f, bq = 0.f;
            #pragma unroll
            for (int w = 0; w < 8; w++) { a += sb[w][c]; bq += qb[w][c]; }
            ssum[c] = a * invT; qsum[c] = bq * invT;
        }
        float tot = 0.f;
        #pragma unroll
        for (int m = 0; m < 4; m++) {
            float mr = ssum[m], mi = ssum[m + 4];
            tot += qsum[m] + qsum[m + 4] - mr * mr - mi * mi;
        }
        #pragma unroll
        for (int j = 0; j < 8; j++) g_mean[(b * FF + f) * 8 + j] = ssum[j];
        g_inv[b * FF + f] = rsqrtf(fmaxf(tot, 1e-10f));
    }
}

// ---------------- K2: SCM pair features ----------------
__global__ void feat_kernel(const float* __restrict__ x,
                            const float* __restrict__ expo,
                            const float* __restrict__ ipd) {
    int bt = blockIdx.x;
    int b  = bt / TT;

    for (int f = threadIdx.x; f < FF; f += blockDim.x) {
        const float* px = x + ((size_t)bt * FF + f) * 8;
        const float* mn = g_mean + (b * FF + f) * 8;
        float inv = g_inv[b * FF + f];

        float vr[4], vi[4];
        #pragma unroll
        for (int m = 0; m < 4; m++) {
            vr[m] = (px[m]     - mn[m])     * inv;
            vi[m] = (px[m + 4] - mn[m + 4]) * inv;
        }
        float s1 = 1.0f / (1.0f + expf(-expo[f]));
        float s2 = 1.0f / (1.0f + expf(-ipd[f]));

        const int ia[10] = {0,0,0,0,1,1,1,2,2,3};
        const int ja[10] = {0,1,2,3,1,2,3,2,3,3};
        float* ob = g_xs + (size_t)bt * C2P * FF + f;

        #pragma unroll
        for (int p = 0; p < 10; p++) {
            float re = vr[ia[p]] * vr[ja[p]] + vi[ia[p]] * vi[ja[p]];
            float im = vi[ia[p]] * vr[ja[p]] - vr[ia[p]] * vi[ja[p]];
            float a  = sqrtf(re * re + im * im);
            float beta = (a > 0.f) ? exp2f(s1 * log2f(a)) : 0.f;
            float mag  = a / (beta + 1e-10f);
            float ang  = atan2f(im, re) * s2;
            float sn, cs;
            sincosf(ang, &sn, &cs);
            ob[(size_t)(2 * p)     * FF] = mag * cs;
            ob[(size_t)(2 * p + 1) * FF] = mag * sn;
        }
    }
}

// ---------------- K3: fused conv1d (SAME,K=5) + LayerNorm ----------------
// 512 threads: warp w -> d rows [8w, 8w+8); lane -> f = lane + 32u, u=0..7.
// Outputs live in registers (8d x 8f as 32 FFMA2 accumulators). No y_s.
// Weights: uniform-per-warp broadcast LDS. Inputs: coalesced LDS.32 feeding 8 d.
extern __shared__ float smem[];

__global__ void __launch_bounds__(NTH, 1)
conv_ln_kernel(const float* __restrict__ conv_b,
               const float* __restrict__ ln_w,
               const float* __restrict__ ln_b,
               float* __restrict__ out) {
    int bt = blockIdx.x;
    int b  = bt / TT;
    int t  = bt % TT;
    int tid = threadIdx.x;
    int warp = tid >> 5, lane = tid & 31;
    int d0 = warp * 8;

    float* w_s  = smem;                  // 100*128 = 12800 floats
    float* in_s = smem + 100 * DD;       // 100*257 = 25700 floats
    float* red  = in_s + 100 * FF;       // 34

    // stage weights [j][d] (coalesced)
    for (int i = tid; i < 100 * DD; i += NTH) w_s[i] = g_wt[i];

    // stage full-width input rows j = c*5+k at time t+k-2 (zero-padded in t)
    for (int li = tid; li < 100 * FF; li += NTH) {
        int kc = li / FF;
        int fl = li - kc * FF;
        int c  = kc / 5;
        int k  = kc - c * 5;
        int tt = t + k - 2;
        float v = 0.f;
        if (tt >= 0 && tt < TT)
            v = g_xs[((size_t)(b * TT + tt) * C2P + c) * FF + fl];
        in_s[li] = v;
    }
    __syncthreads();

    // main conv: acc[dd][p] covers d=d0+dd, f = lane + 32*(2p) / lane + 32*(2p+1)
    ull acc[8][4];
    #pragma unroll
    for (int dd = 0; dd < 8; dd++)
        #pragma unroll
        for (int p = 0; p < 4; p++) acc[dd][p] = 0ull;

    for (int j = 0; j < 100; j++) {
        const float* row = in_s + j * FF + lane;
        float x0 = row[0],   x1 = row[32],  x2 = row[64],  x3 = row[96];
        float x4 = row[128], x5 = row[160], x6 = row[192], x7 = row[224];
        ull X0 = packab(x0, x1), X1 = packab(x2, x3);
        ull X2 = packab(x4, x5), X3 = packab(x6, x7);

        const float4* wp = (const float4*)(w_s + j * DD + d0);
        float4 wa = wp[0], wb = wp[1];
        ull W0 = pack2(wa.x), W1 = pack2(wa.y), W2 = pack2(wa.z), W3 = pack2(wa.w);
        ull W4 = pack2(wb.x), W5 = pack2(wb.y), W6 = pack2(wb.z), W7 = pack2(wb.w);

        fma2(acc[0][0], W0, X0); fma2(acc[0][1], W0, X1); fma2(acc[0][2], W0, X2); fma2(acc[0][3], W0, X3);
        fma2(acc[1][0], W1, X0); fma2(acc[1][1], W1, X1); fma2(acc[1][2], W1, X2); fma2(acc[1][3], W1, X3);
        fma2(acc[2][0], W2, X0); fma2(acc[2][1], W2, X1); fma2(acc[2][2], W2, X2); fma2(acc[2][3], W2, X3);
        fma2(acc[3][0], W3, X0); fma2(acc[3][1], W3, X1); fma2(acc[3][2], W3, X2); fma2(acc[3][3], W3, X3);
        fma2(acc[4][0], W4, X0); fma2(acc[4][1], W4, X1); fma2(acc[4][2], W4, X2); fma2(acc[4][3], W4, X3);
        fma2(acc[5][0], W5, X0); fma2(acc[5][1], W5, X1); fma2(acc[5][2], W5, X2); fma2(acc[5][3], W5, X3);
        fma2(acc[6][0], W6, X0); fma2(acc[6][1], W6, X1); fma2(acc[6][2], W6, X2); fma2(acc[6][3], W6, X3);
        fma2(acc[7][0], W7, X0); fma2(acc[7][1], W7, X1); fma2(acc[7][2], W7, X2); fma2(acc[7][3], W7, X3);
    }

    // tail column f = 256: lanes split j, then warp-reduce
    float acct[8];
    #pragma unroll
    for (int dd = 0; dd < 8; dd++) acct[dd] = 0.f;
    for (int jj = lane; jj < 100; jj += 32) {
        float xv = in_s[jj * FF + 256];
        const float* wj = w_s + jj * DD + d0;
        #pragma unroll
        for (int dd = 0; dd < 8; dd++) acct[dd] = fmaf(wj[dd], xv, acct[dd]);
    }
    #pragma unroll
    for (int dd = 0; dd < 8; dd++) {
        #pragma unroll
        for (int o = 16; o > 0; o >>= 1)
            acct[dd] += __shfl_xor_sync(0xffffffffu, acct[dd], o);
    }

    // unpack + bias
    const float4* bp = (const float4*)(conv_b + d0);
    float4 b4a = bp[0], b4b = bp[1];
    float bias[8] = {b4a.x, b4a.y, b4a.z, b4a.w, b4b.x, b4b.y, b4b.z, b4b.w};

    float yv[8][8];
    #pragma unroll
    for (int dd = 0; dd < 8; dd++) {
        #pragma unroll
        for (int p = 0; p < 4; p++) {
            float2 pr = unpack2(acc[dd][p]);
            yv[dd][2*p]   = pr.x + bias[dd];
            yv[dd][2*p+1] = pr.y + bias[dd];
        }
        acct[dd] += bias[dd];
    }

    // LN stats from registers
    float s = 0.f, q = 0.f;
    #pragma unroll
    for (int dd = 0; dd < 8; dd++)
        #pragma unroll
        for (int u = 0; u < 8; u++) {
            float v = yv[dd][u];
            s += v; q += v * v;
        }
    if (lane == 0) {
        #pragma unroll
        for (int dd = 0; dd < 8; dd++) { s += acct[dd]; q += acct[dd] * acct[dd]; }
    }
    #pragma unroll
    for (int o = 16; o > 0; o >>= 1) {
        s += __shfl_xor_sync(0xffffffffu, s, o);
        q += __shfl_xor_sync(0xffffffffu, q, o);
    }
    if (lane == 0) { red[warp] = s; red[16 + warp] = q; }
    __syncthreads();
    if (tid < 32) {
        s = (tid < 16) ? red[tid] : 0.f;
        q = (tid < 16) ? red[16 + tid] : 0.f;
        #pragma unroll
        for (int o = 8; o > 0; o >>= 1) {
            s += __shfl_xor_sync(0xffffffffu, s, o);
            q += __shfl_xor_sync(0xffffffffu, q, o);
        }
        if (tid == 0) {
            const float invN = 1.0f / (float)NLN;
            float mu  = s * invN;
            float var = q * invN - mu * mu;
            red[32] = mu;
            red[33] = rsqrtf(var + 1e-5f);
        }
    }
    __syncthreads();
    float mu = red[32], rs = red[33];

    // normalize + store (coalesced within warp)
    float* po = out + (size_t)bt * NLN;
    #pragma unroll
    for (int dd = 0; dd < 8; dd++) {
        int rowo = (d0 + dd) * FF;
        #pragma unroll
        for (int u = 0; u < 8; u++) {
            int oi = rowo + lane + 32 * u;
            po[oi] = (yv[dd][u] - mu) * rs * ln_w[oi] + ln_b[oi];
        }
        if (lane == 0) {
            int oi = rowo + 256;
            po[oi] = (acct[dd] - mu) * rs * ln_w[oi] + ln_b[oi];
        }
    }
}

// ---------------- launch ----------------
extern "C" void kernel_launch(void* const* d_in, const int* in_sizes, int n_in,
                              void* d_out, int out_size) {
    const float* x    = (const float*)d_in[0];
    const float* expo = (const float*)d_in[1];
    const float* ipd  = (const float*)d_in[2];
    const float* cw   = (const float*)d_in[3];
    const float* cb   = (const float*)d_in[4];
    const float* lw   = (const float*)d_in[5];
    const float* lb   = (const float*)d_in[6];
    float* out = (float*)d_out;

    wtrans_kernel<<<1, 256>>>(cw);
    stats_kernel<<<dim3(BB, FF), 256>>>(x);
    feat_kernel<<<BB * TT, 256>>>(x, expo, ipd);

    int smem_bytes = (100 * DD + 100 * FF + 34) * (int)sizeof(float); // 154,136 B
    cudaFuncSetAttribute(conv_ln_kernel,
                         cudaFuncAttributeMaxDynamicSharedMemorySize, smem_bytes);
    conv_ln_kernel<<<BB * TT, NTH, smem_bytes>>>(cb, lw, lb, out);
}

// round 7
// speedup vs baseline: 2.2891x; 1.0137x over previous
#include <cuda_runtime.h>
#include <math.h>

#define BB 4
#define TT 512
#define FF 257
#define FPI 258              // padded in_s row (even -> 8B-aligned f-pairs)
#define DD 128
#define C2P 20
#define NLN (DD*FF)          // 32896
#define NTH 512

typedef unsigned long long ull;

__device__ __forceinline__ void fma2(ull &acc, ull a, ull b) {
    asm("fma.rn.f32x2 %0, %1, %2, %0;" : "+l"(acc) : "l"(a), "l"(b));
}
__device__ __forceinline__ ull pack2(float v) {
    ull r; unsigned u = __float_as_uint(v);
    asm("mov.b64 %0, {%1, %1};" : "=l"(r) : "r"(u));
    return r;
}
__device__ __forceinline__ float2 unpack2(ull v) {
    unsigned lo, hi;
    asm("mov.b64 {%0, %1}, %2;" : "=r"(lo), "=r"(hi) : "l"(v));
    return make_float2(__uint_as_float(lo), __uint_as_float(hi));
}

// ---------------- device scratch ----------------
__device__ float g_xs[(size_t)BB*TT*C2P*FF];   // features [B][T][C][F]
__device__ float g_mean[BB*FF*8];
__device__ float g_inv[BB*FF];
__device__ float g_wt[100*DD];                 // transposed weights [j][d]

// ---------------- K0: weight transpose ----------------
__global__ void wtrans_kernel(const float* __restrict__ conv_w) {
    for (int i = threadIdx.x; i < DD * 100; i += blockDim.x) {
        int d = i / 100, j = i - d * 100;
        g_wt[j * DD + d] = conv_w[i];
    }
}

// ---------------- K1: time stats, one block per (b,f) ----------------
__global__ void stats_kernel(const float* __restrict__ x) {
    int b = blockIdx.x;
    int f = blockIdx.y;
    int tid = threadIdx.x;          // 256
    int ch = tid & 7;
    int tl = tid >> 3;

    float s = 0.f, q = 0.f;
    const float* px = x + ((size_t)b * TT * FF + f) * 8 + ch;
    #pragma unroll 4
    for (int t = tl; t < TT; t += 32) {
        float v = px[(size_t)t * FF * 8];
        s += v; q += v * v;
    }
    s += __shfl_xor_sync(0xffffffffu, s, 8);
    q += __shfl_xor_sync(0xffffffffu, q, 8);
    s += __shfl_xor_sync(0xffffffffu, s, 16);
    q += __shfl_xor_sync(0xffffffffu, q, 16);

    __shared__ float sb[8][8], qb[8][8];
    int warp = tid >> 5, lane = tid & 31;
    if (lane < 8) { sb[warp][lane] = s; qb[warp][lane] = q; }
    __syncthreads();

    if (tid == 0) {
        const float invT = 1.0f / (float)TT;
        float ssum[8], qsum[8];
        #pragma unroll
        for (int c = 0; c < 8; c++) {
            float a = 0.f, bq = 0.f;
            #pragma unroll
            for (int w = 0; w < 8; w++) { a += sb[w][c]; bq += qb[w][c]; }
            ssum[c] = a * invT; qsum[c] = bq * invT;
        }
        float tot = 0.f;
        #pragma unroll
        for (int m = 0; m < 4; m++) {
            float mr = ssum[m], mi = ssum[m + 4];
            tot += qsum[m] + qsum[m + 4] - mr * mr - mi * mi;
        }
        #pragma unroll
        for (int j = 0; j < 8; j++) g_mean[(b * FF + f) * 8 + j] = ssum[j];
        g_inv[b * FF + f] = rsqrtf(fmaxf(tot, 1e-10f));
    }
}

// ---------------- K2: SCM pair features ----------------
__global__ void feat_kernel(const float* __restrict__ x,
                            const float* __restrict__ expo,
                            const float* __restrict__ ipd) {
    int bt = blockIdx.x;
    int b  = bt / TT;

    for (int f = threadIdx.x; f < FF; f += blockDim.x) {
        const float* px = x + ((size_t)bt * FF + f) * 8;
        const float* mn = g_mean + (b * FF + f) * 8;
        float inv = g_inv[b * FF + f];

        float vr[4], vi[4];
        #pragma unroll
        for (int m = 0; m < 4; m++) {
            vr[m] = (px[m]     - mn[m])     * inv;
            vi[m] = (px[m + 4] - mn[m + 4]) * inv;
        }
        float s1 = 1.0f / (1.0f + expf(-expo[f]));
        float s2 = 1.0f / (1.0f + expf(-ipd[f]));

        const int ia[10] = {0,0,0,0,1,1,1,2,2,3};
        const int ja[10] = {0,1,2,3,1,2,3,2,3,3};
        float* ob = g_xs + (size_t)bt * C2P * FF + f;

        #pragma unroll
        for (int p = 0; p < 10; p++) {
            float re = vr[ia[p]] * vr[ja[p]] + vi[ia[p]] * vi[ja[p]];
            float im = vi[ia[p]] * vr[ja[p]] - vr[ia[p]] * vi[ja[p]];
            float a  = sqrtf(re * re + im * im);
            float beta = (a > 0.f) ? exp2f(s1 * log2f(a)) : 0.f;
            float mag  = a / (beta + 1e-10f);
            float ang  = atan2f(im, re) * s2;
            float sn, cs;
            sincosf(ang, &sn, &cs);
            ob[(size_t)(2 * p)     * FF] = mag * cs;
            ob[(size_t)(2 * p + 1) * FF] = mag * sn;
        }
    }
}

// ---------------- K3: fused conv1d (SAME,K=5) + LayerNorm ----------------
// 512 threads: warp w -> d rows [8w,8w+8); lane -> f-pairs {2*lane,2*lane+1}+64u.
// Accumulators stay packed (32 ull) through the whole epilogue.
extern __shared__ float smem[];

__global__ void __launch_bounds__(NTH, 1)
conv_ln_kernel(const float* __restrict__ conv_b,
               const float* __restrict__ ln_w,
               const float* __restrict__ ln_b,
               float* __restrict__ out) {
    int bt = blockIdx.x;
    int b  = bt / TT;
    int t  = bt % TT;
    int tid = threadIdx.x;
    int warp = tid >> 5, lane = tid & 31;
    int d0 = warp * 8;

    float* w_s  = smem;                  // 100*128 = 12800 floats
    float* in_s = smem + 100 * DD;       // 100*258 = 25800 floats
    float* red  = in_s + 100 * FPI;      // 34

    // stage weights [j][d] (coalesced)
    for (int i = tid; i < 100 * DD; i += NTH) w_s[i] = g_wt[i];

    // stage input rows, division-free: warp per row, lanes stride f
    for (int kc = warp; kc < 100; kc += 16) {
        int c = kc / 5;                  // warp-uniform, cheap
        int k = kc - c * 5;
        int tt = t + k - 2;
        float* dst = in_s + kc * FPI;
        if (tt >= 0 && tt < TT) {
            const float* src = g_xs + ((size_t)(b * TT + tt) * C2P + c) * FF;
            for (int fl = lane; fl < FF; fl += 32) dst[fl] = src[fl];
        } else {
            for (int fl = lane; fl < FF; fl += 32) dst[fl] = 0.f;
        }
        if (lane == 0) dst[FF] = 0.f;    // pad column
    }
    __syncthreads();

    // main conv: acc[dd][u] = packed y for d=d0+dd, f = {2*lane, 2*lane+1} + 64u
    ull acc[8][4];
    #pragma unroll
    for (int dd = 0; dd < 8; dd++)
        #pragma unroll
        for (int u = 0; u < 4; u++) acc[dd][u] = 0ull;

    const float* rowbase = in_s + 2 * lane;
    const float4* wbase  = (const float4*)(w_s + d0);

    #pragma unroll 5
    for (int j = 0; j < 100; j++) {
        const ull* rp = (const ull*)(rowbase + j * FPI);
        ull X0 = rp[0], X1 = rp[32], X2 = rp[64], X3 = rp[96];

        const float4* wp = wbase + j * (DD / 4);
        float4 wa = wp[0], wb = wp[1];
        ull W0 = pack2(wa.x), W1 = pack2(wa.y), W2 = pack2(wa.z), W3 = pack2(wa.w);
        ull W4 = pack2(wb.x), W5 = pack2(wb.y), W6 = pack2(wb.z), W7 = pack2(wb.w);

        fma2(acc[0][0], W0, X0); fma2(acc[0][1], W0, X1); fma2(acc[0][2], W0, X2); fma2(acc[0][3], W0, X3);
        fma2(acc[1][0], W1, X0); fma2(acc[1][1], W1, X1); fma2(acc[1][2], W1, X2); fma2(acc[1][3], W1, X3);
        fma2(acc[2][0], W2, X0); fma2(acc[2][1], W2, X1); fma2(acc[2][2], W2, X2); fma2(acc[2][3], W2, X3);
        fma2(acc[3][0], W3, X0); fma2(acc[3][1], W3, X1); fma2(acc[3][2], W3, X2); fma2(acc[3][3], W3, X3);
        fma2(acc[4][0], W4, X0); fma2(acc[4][1], W4, X1); fma2(acc[4][2], W4, X2); fma2(acc[4][3], W4, X3);
        fma2(acc[5][0], W5, X0); fma2(acc[5][1], W5, X1); fma2(acc[5][2], W5, X2); fma2(acc[5][3], W5, X3);
        fma2(acc[6][0], W6, X0); fma2(acc[6][1], W6, X1); fma2(acc[6][2], W6, X2); fma2(acc[6][3], W6, X3);
        fma2(acc[7][0], W7, X0); fma2(acc[7][1], W7, X1); fma2(acc[7][2], W7, X2); fma2(acc[7][3], W7, X3);
    }

    // tail column f = 256: lanes split j, warp-reduce
    float acct[8];
    #pragma unroll
    for (int dd = 0; dd < 8; dd++) acct[dd] = 0.f;
    for (int jj = lane; jj < 100; jj += 32) {
        float xv = in_s[jj * FPI + 256];
        const float* wj = w_s + jj * DD + d0;
        #pragma unroll
        for (int dd = 0; dd < 8; dd++) acct[dd] = fmaf(wj[dd], xv, acct[dd]);
    }
    #pragma unroll
    for (int dd = 0; dd < 8; dd++) {
        #pragma unroll
        for (int o = 16; o > 0; o >>= 1)
            acct[dd] += __shfl_xor_sync(0xffffffffu, acct[dd], o);
    }

    const float4* bp = (const float4*)(conv_b + d0);
    float4 b4a = bp[0], b4b = bp[1];
    float bias[8] = {b4a.x, b4a.y, b4a.z, b4a.w, b4b.x, b4b.y, b4b.z, b4b.w};
    #pragma unroll
    for (int dd = 0; dd < 8; dd++) acct[dd] += bias[dd];

    // LN stats straight from packed accumulators (+bias on the fly)
    float s = 0.f, q = 0.f;
    #pragma unroll
    for (int dd = 0; dd < 8; dd++) {
        #pragma unroll
        for (int u = 0; u < 4; u++) {
            float2 pr = unpack2(acc[dd][u]);
            float v0 = pr.x + bias[dd], v1 = pr.y + bias[dd];
            s += v0 + v1; q += v0 * v0 + v1 * v1;
        }
    }
    if (lane == 0) {
        #pragma unroll
        for (int dd = 0; dd < 8; dd++) { s += acct[dd]; q += acct[dd] * acct[dd]; }
    }
    #pragma unroll
    for (int o = 16; o > 0; o >>= 1) {
        s += __shfl_xor_sync(0xffffffffu, s, o);
        q += __shfl_xor_sync(0xffffffffu, q, o);
    }
    if (lane == 0) { red[warp] = s; red[16 + warp] = q; }
    __syncthreads();
    if (tid < 32) {
        s = (tid < 16) ? red[tid] : 0.f;
        q = (tid < 16) ? red[16 + tid] : 0.f;
        #pragma unroll
        for (int o = 8; o > 0; o >>= 1) {
            s += __shfl_xor_sync(0xffffffffu, s, o);
            q += __shfl_xor_sync(0xffffffffu, q, o);
        }
        if (tid == 0) {
            const float invN = 1.0f / (float)NLN;
            float mu  = s * invN;
            float var = q * invN - mu * mu;
            red[32] = mu;
            red[33] = rsqrtf(var + 1e-5f);
        }
    }
    __syncthreads();
    float mu = red[32], rs = red[33];

    // normalize + store: SCALAR accesses (row base (d*257) can be odd -> no
    // 8B vector ops on out/ln_w/ln_b). Two scalars per packed accumulator.
    float* po = out + (size_t)bt * NLN;
    #pragma unroll
    for (int dd = 0; dd < 8; dd++) {
        int rowo = (d0 + dd) * FF;
        #pragma unroll
        for (int u = 0; u < 4; u++) {
            int oi = rowo + 2 * lane + 64 * u;
            float2 pr = unpack2(acc[dd][u]);
            po[oi]     = (pr.x + bias[dd] - mu) * rs * ln_w[oi]     + ln_b[oi];
            po[oi + 1] = (pr.y + bias[dd] - mu) * rs * ln_w[oi + 1] + ln_b[oi + 1];
        }
        if (lane == 0) {
            int oi = rowo + 256;
            po[oi] = (acct[dd] - mu) * rs * ln_w[oi] + ln_b[oi];
        }
    }
}

// ---------------- launch ----------------
extern "C" void kernel_launch(void* const* d_in, const int* in_sizes, int n_in,
                              void* d_out, int out_size) {
    const float* x    = (const float*)d_in[0];
    const float* expo = (const float*)d_in[1];
    const float* ipd  = (const float*)d_in[2];
    const float* cw   = (const float*)d_in[3];
    const float* cb   = (const float*)d_in[4];
    const float* lw   = (const float*)d_in[5];
    const float* lb   = (const float*)d_in[6];
    float* out = (float*)d_out;

    wtrans_kernel<<<1, 256>>>(cw);
    stats_kernel<<<dim3(BB, FF), 256>>>(x);
    feat_kernel<<<BB * TT, 256>>>(x, expo, ipd);

    int smem_bytes = (100 * DD + 100 * FPI + 40) * (int)sizeof(float); // 154,560 B
    cudaFuncSetAttribute(conv_ln_kernel,
                         cudaFuncAttributeMaxDynamicSharedMemorySize, smem_bytes);
    conv_ln_kernel<<<BB * TT, NTH, smem_bytes>>>(cb, lw, lb, out);
}